// round 1
// baseline (speedup 1.0000x reference)
#include <cuda_runtime.h>

#define TPB  128    // threads per block == N points per batch row
#define LVL  6      // grid levels
#define DD   4      // feature dim per level
#define DIRD 16     // direction feature dim
#define HD   64     // hidden dim
#define IN0  34     // DIRD + LVL*(DD-1)
#define ROWS 16     // batch rows processed per block (amortize weight staging)

// ---- packed f32x2 helpers (FFMA2 is PTX-only; ptxas won't auto-fuse) ----
__device__ __forceinline__ unsigned long long pk2(float lo, float hi) {
    unsigned long long r;
    asm("mov.b64 %0, {%1, %2};" : "=l"(r) : "f"(lo), "f"(hi));
    return r;
}
__device__ __forceinline__ void up2(unsigned long long v, float& lo, float& hi) {
    asm("mov.b64 {%0, %1}, %2;" : "=f"(lo), "=f"(hi) : "l"(v));
}
__device__ __forceinline__ unsigned long long fma2(unsigned long long a,
                                                   unsigned long long b,
                                                   unsigned long long c) {
    unsigned long long r;
    asm("fma.rn.f32x2 %0, %1, %2, %3;" : "=l"(r) : "l"(a), "l"(b), "l"(c));
    return r;
}

__global__ __launch_bounds__(TPB) void surf_kernel(
    const int*   __restrict__ x,      // (B, 128, 6)
    const float* __restrict__ dirs,   // (B, 16)
    const float* __restrict__ gw,     // (4194304, 4)
    const float* __restrict__ W0, const float* __restrict__ b0,
    const float* __restrict__ W1, const float* __restrict__ b1,
    const float* __restrict__ W2, const float* __restrict__ b2,
    float* __restrict__ outSig,       // (B*128)
    float* __restrict__ outCol,       // (B*3)
    int B)
{
    __shared__ __align__(16) float sW0[IN0 * HD];
    __shared__ __align__(16) float sW1[HD * HD];
    __shared__ __align__(16) float sW2[HD * 3];
    __shared__ __align__(16) float sb0[HD];
    __shared__ __align__(16) float sb1[HD];
    __shared__ float sb2v[3];
    __shared__ float sdir[DIRD];
    __shared__ float s0arr[TPB];
    __shared__ float wred[4];
    __shared__ float cred[4][3];

    const int tid  = threadIdx.x;
    const int lane = tid & 31;
    const int wid  = tid >> 5;

    // stage weights once per block (hot in L2 across blocks)
    for (int i = tid; i < IN0 * HD; i += TPB) sW0[i] = W0[i];
    for (int i = tid; i < HD * HD;  i += TPB) sW1[i] = W1[i];
    for (int i = tid; i < HD * 3;   i += TPB) sW2[i] = W2[i];
    if (tid < HD) { sb0[tid] = b0[tid]; sb1[tid] = b1[tid]; }
    if (tid < 3)  sb2v[tid] = b2[tid];

    for (int r = 0; r < ROWS; ++r) {
        const int b = blockIdx.x * ROWS + r;
        if (b >= B) break;
        __syncthreads();   // protect sdir/s0arr/wred/cred reuse across rows
        if (tid < DIRD) sdir[tid] = dirs[b * DIRD + tid];

        // ---- embedding gather: 6 levels x float4 ----
        float feat[LVL][DD];
        const int* xp = x + ((long long)b * TPB + tid) * LVL;
        #pragma unroll
        for (int l = 0; l < LVL; ++l) {
            const int idx = __ldg(xp + l);
            const float4 f = *(const float4*)(gw + (long long)idx * DD);
            feat[l][0] = f.x; feat[l][1] = f.y; feat[l][2] = f.z; feat[l][3] = f.w;
        }

        // ---- density: prod of clipped channel-0 over levels ----
        float s = 1.f;
        #pragma unroll
        for (int l = 0; l < LVL; ++l) s *= fminf(fmaxf(feat[l][0], 0.f), 1.f);
        s += 1e-4f;
        s0arr[tid] = s;

        // per-row max over the 128 points
        float m = s;
        #pragma unroll
        for (int o = 16; o; o >>= 1) m = fmaxf(m, __shfl_xor_sync(0xffffffffu, m, o));
        if (lane == 0) wred[wid] = m;
        __syncthreads();
        m = fmaxf(fmaxf(wred[0], wred[1]), fmaxf(wred[2], wred[3]));
        const float inv_m = 1.f / m;
        const float sigma = s * inv_m;
        outSig[(long long)b * TPB + tid] = sigma;

        // cumprod over a size-1 axis is identity => weight = alpha[n-1]*sigma[n]
        const float cw = (tid == 0) ? sigma
                                    : (1.f - s0arr[tid - 1] * inv_m) * sigma;

        // ---- layer 0: 34 -> 64 (packed f32x2 accumulators) ----
        unsigned long long acc[HD / 2];
        #pragma unroll
        for (int j = 0; j < HD / 2; ++j)
            acc[j] = *(const unsigned long long*)&sb0[2 * j];

        #pragma unroll
        for (int i = 0; i < DIRD; ++i) {
            const unsigned long long a = pk2(sdir[i], sdir[i]);
            const unsigned long long* wrow = (const unsigned long long*)&sW0[i * HD];
            #pragma unroll
            for (int j = 0; j < HD / 2; ++j) acc[j] = fma2(a, wrow[j], acc[j]);
        }
        #pragma unroll
        for (int l = 0; l < LVL; ++l) {
            #pragma unroll
            for (int c = 1; c < DD; ++c) {
                const int i = DIRD + l * (DD - 1) + (c - 1);
                const unsigned long long a = pk2(feat[l][c], feat[l][c]);
                const unsigned long long* wrow = (const unsigned long long*)&sW0[i * HD];
                #pragma unroll
                for (int j = 0; j < HD / 2; ++j) acc[j] = fma2(a, wrow[j], acc[j]);
            }
        }

        float h[HD];
        #pragma unroll
        for (int j = 0; j < HD / 2; ++j) {
            float lo, hi; up2(acc[j], lo, hi);
            h[2 * j]     = fmaxf(lo, 0.f);
            h[2 * j + 1] = fmaxf(hi, 0.f);
        }

        // ---- layer 1: 64 -> 64 ----
        #pragma unroll
        for (int j = 0; j < HD / 2; ++j)
            acc[j] = *(const unsigned long long*)&sb1[2 * j];
        #pragma unroll
        for (int i = 0; i < HD; ++i) {
            const unsigned long long a = pk2(h[i], h[i]);
            const unsigned long long* wrow = (const unsigned long long*)&sW1[i * HD];
            #pragma unroll
            for (int j = 0; j < HD / 2; ++j) acc[j] = fma2(a, wrow[j], acc[j]);
        }

        // ---- layer 2: 64 -> 3, relu folded in ----
        float c0 = sb2v[0], c1 = sb2v[1], c2 = sb2v[2];
        #pragma unroll
        for (int j = 0; j < HD / 2; ++j) {
            float lo, hi; up2(acc[j], lo, hi);
            lo = fmaxf(lo, 0.f); hi = fmaxf(hi, 0.f);
            c0 += lo * sW2[(2 * j) * 3 + 0] + hi * sW2[(2 * j + 1) * 3 + 0];
            c1 += lo * sW2[(2 * j) * 3 + 1] + hi * sW2[(2 * j + 1) * 3 + 1];
            c2 += lo * sW2[(2 * j) * 3 + 2] + hi * sW2[(2 * j + 1) * 3 + 2];
        }
        // sigmoid * compositing weight
        c0 = cw / (1.f + __expf(-c0));
        c1 = cw / (1.f + __expf(-c1));
        c2 = cw / (1.f + __expf(-c2));

        // ---- reduce color over the 128 points of this row ----
        #pragma unroll
        for (int o = 16; o; o >>= 1) {
            c0 += __shfl_xor_sync(0xffffffffu, c0, o);
            c1 += __shfl_xor_sync(0xffffffffu, c1, o);
            c2 += __shfl_xor_sync(0xffffffffu, c2, o);
        }
        if (lane == 0) { cred[wid][0] = c0; cred[wid][1] = c1; cred[wid][2] = c2; }
        __syncthreads();
        if (tid < 3)
            outCol[(long long)b * 3 + tid] =
                cred[0][tid] + cred[1][tid] + cred[2][tid] + cred[3][tid];
    }
}

extern "C" void kernel_launch(void* const* d_in, const int* in_sizes, int n_in,
                              void* d_out, int out_size) {
    const int*   x   = (const int*)  d_in[0];
    const float* d   = (const float*)d_in[1];
    const float* gw  = (const float*)d_in[2];
    const float* W0  = (const float*)d_in[3];
    const float* b0  = (const float*)d_in[4];
    const float* W1  = (const float*)d_in[5];
    const float* b1  = (const float*)d_in[6];
    const float* W2  = (const float*)d_in[7];
    const float* b2  = (const float*)d_in[8];

    const int B = in_sizes[1] / DIRD;           // d is (B, 16)
    float* out = (float*)d_out;
    float* outSig = out;                        // (B*128) then (B*3)
    float* outCol = out + (long long)B * TPB;

    const int blocks = (B + ROWS - 1) / ROWS;
    surf_kernel<<<blocks, TPB>>>(x, d, gw, W0, b0, W1, b1, W2, b2,
                                 outSig, outCol, B);
}

// round 4
// speedup vs baseline: 1.4606x; 1.4606x over previous
#include <cuda_runtime.h>
#include <cuda_bf16.h>
#include <cstdint>

#define TPB  128
#define ROWS 8
#define LVL  6
#define DIRD 16
#define HD   64

// ---- dynamic smem offsets (bytes) ----
#define BF_OFF    0u        // B-fragment table: 96 slots * 32 lanes * 8B = 24576
#define A0H_OFF   24576u    // A0 hi tile: 128 rows * 80B = 10240
#define A0L_OFF   34816u    // A0 lo tile: 10240
#define W0D_OFF   45056u    // W0 dir part fp32 [16][64] = 4096
#define W2S_OFF   49152u    // W2 as float4[64] = 1024
#define BIASP_OFF 50176u    // bias' fp32[64]
#define B0S_OFF   50432u
#define B1S_OFF   50688u
#define SDIR_OFF  50944u    // fp32[16]
#define SS0_OFF   51008u    // fp32[128]
#define SCW_OFF   51520u    // fp32[128]
#define WRED_OFF  52032u    // fp32[4]
#define CRED_OFF  52048u    // fp32[12]
#define SB2_OFF   52096u    // fp32[4]  (b2, the bias R3 dropped)
#define SMEM_TOTAL 52112u

#define A0_PITCH_U32 20     // 40 bf16 = 80B pitch (conflict-free fragment loads)

// pack two floats to bf16x2 (lo -> low half)
__device__ __forceinline__ void split2(float f0, float f1, uint32_t& hi, uint32_t& lo) {
    __nv_bfloat162 h = __floats2bfloat162_rn(f0, f1);   // x=f0 (low), y=f1 (high)
    hi = *(uint32_t*)&h;
    float2 hf = __bfloat1622float2(h);
    __nv_bfloat162 l = __floats2bfloat162_rn(f0 - hf.x, f1 - hf.y);
    lo = *(uint32_t*)&l;
}

__device__ __forceinline__ void mma_bf16(float d[4], const uint32_t a[4], uint2 b) {
    asm volatile("mma.sync.aligned.m16n8k16.row.col.f32.bf16.bf16.f32 "
        "{%0,%1,%2,%3}, {%4,%5,%6,%7}, {%8,%9}, {%0,%1,%2,%3};"
        : "+f"(d[0]), "+f"(d[1]), "+f"(d[2]), "+f"(d[3])
        : "r"(a[0]), "r"(a[1]), "r"(a[2]), "r"(a[3]), "r"(b.x), "r"(b.y));
}

__global__ __launch_bounds__(TPB, 3) void surf_mma(
    const int*   __restrict__ x,
    const float* __restrict__ dirs,
    const float* __restrict__ gw,
    const float* __restrict__ W0, const float* __restrict__ b0,
    const float* __restrict__ W1, const float* __restrict__ b1,
    const float* __restrict__ W2, const float* __restrict__ b2,
    float* __restrict__ outSig, float* __restrict__ outCol, int Btot)
{
    extern __shared__ char sm[];
    const int tid = threadIdx.x, lane = tid & 31, wid = tid >> 5;
    const int g = lane >> 2, tg = lane & 3;

    // ================= one-time staging per CTA =================
    for (int i = tid; i < DIRD * HD; i += TPB)
        ((float*)(sm + W0D_OFF))[i] = W0[i];
    if (tid < HD) {
        float4 v; v.x = W2[tid * 3]; v.y = W2[tid * 3 + 1]; v.z = W2[tid * 3 + 2]; v.w = 0.f;
        ((float4*)(sm + W2S_OFF))[tid] = v;
        ((float*)(sm + B0S_OFF))[tid] = b0[tid];
        ((float*)(sm + B1S_OFF))[tid] = b1[tid];
    }
    if (tid < 3) ((float*)(sm + SB2_OFF))[tid] = b2[tid];
    // B fragments: layer0 slots 0..31 (hl*16+ks*8+j), layer1 slots 32..95 (32+hl*32+ks*8+j)
    uint2* bf = (uint2*)(sm + BF_OFF);
    for (int e = tid; e < 96 * 32; e += TPB) {
        const int s = e >> 5, ln = e & 31;
        const int lg = ln >> 2, ltg = ln & 3;
        int layer, hl, ks, j;
        if (s < 32) { layer = 0; hl = s >> 4; ks = (s >> 3) & 1; j = s & 7; }
        else { const int t2 = s - 32; layer = 1; hl = t2 >> 5; ks = (t2 >> 3) & 3; j = t2 & 7; }
        const int n = j * 8 + lg;
        uint32_t regs[2];
        #pragma unroll
        for (int rr = 0; rr < 2; ++rr) {
            const int k0 = ks * 16 + ltg * 2 + rr * 8;
            float wa, wb;
            if (layer == 0) {
                wa = (k0     < 18) ? W0[(16 + k0)     * HD + n] : 0.f;
                wb = (k0 + 1 < 18) ? W0[(16 + k0 + 1) * HD + n] : 0.f;
            } else {
                wa = W1[k0 * HD + n];
                wb = W1[(k0 + 1) * HD + n];
            }
            uint32_t hi, lo;
            split2(wa, wb, hi, lo);
            regs[rr] = hl ? lo : hi;
        }
        uint2 v; v.x = regs[0]; v.y = regs[1];
        bf[s * 32 + ln] = v;
    }
    // zero A0 pad columns 18..31 (u32 idx 9..15)
    for (int e = tid; e < TPB * 7; e += TPB) {
        const int p = e / 7, kk = 9 + (e % 7);
        ((uint32_t*)(sm + A0H_OFF))[p * A0_PITCH_U32 + kk] = 0u;
        ((uint32_t*)(sm + A0L_OFF))[p * A0_PITCH_U32 + kk] = 0u;
    }
    __syncthreads();

    // ================= row loop =================
    for (int r = 0; r < ROWS; ++r) {
        int b = blockIdx.x * ROWS + r;
        if (b >= Btot) b = Btot - 1;   // duplicated identical work; uniform barriers

        if (tid < DIRD) ((float*)(sm + SDIR_OFF))[tid] = dirs[b * DIRD + tid];

        // gather 6 x float4
        float feat[LVL][4];
        const int* xp = x + ((long long)b * TPB + tid) * LVL;
        #pragma unroll
        for (int l = 0; l < LVL; ++l) {
            const int idx = __ldg(xp + l);
            const float4 f = *(const float4*)(gw + (long long)idx * 4);
            feat[l][0] = f.x; feat[l][1] = f.y; feat[l][2] = f.z; feat[l][3] = f.w;
        }
        // density
        float s = 1.f;
        #pragma unroll
        for (int l = 0; l < LVL; ++l) s *= fminf(fmaxf(feat[l][0], 0.f), 1.f);
        s += 1e-4f;
        ((float*)(sm + SS0_OFF))[tid] = s;
        float m = s;
        #pragma unroll
        for (int o = 16; o; o >>= 1) m = fmaxf(m, __shfl_xor_sync(0xffffffffu, m, o));
        if (lane == 0) ((float*)(sm + WRED_OFF))[wid] = m;
        __syncthreads();   // [A]
        {
            const float* wr = (const float*)(sm + WRED_OFF);
            m = fmaxf(fmaxf(wr[0], wr[1]), fmaxf(wr[2], wr[3]));
        }
        const float inv_m = 1.f / m;
        const float sigma = s * inv_m;
        outSig[(long long)b * TPB + tid] = sigma;
        const float cw = (tid == 0) ? sigma
                         : (1.f - ((const float*)(sm + SS0_OFF))[tid - 1] * inv_m) * sigma;
        ((float*)(sm + SCW_OFF))[tid] = cw;

        // write A0 (18 geo dims, hi/lo bf16, point-major)
        {
            float geo[18];
            #pragma unroll
            for (int l = 0; l < LVL; ++l) {
                geo[l * 3 + 0] = feat[l][1];
                geo[l * 3 + 1] = feat[l][2];
                geo[l * 3 + 2] = feat[l][3];
            }
            uint32_t* ah = (uint32_t*)(sm + A0H_OFF) + tid * A0_PITCH_U32;
            uint32_t* al = (uint32_t*)(sm + A0L_OFF) + tid * A0_PITCH_U32;
            #pragma unroll
            for (int kk = 0; kk < 9; ++kk) {
                uint32_t hi, lo;
                split2(geo[2 * kk], geo[2 * kk + 1], hi, lo);
                ah[kk] = hi; al[kk] = lo;
            }
        }
        // bias' = b0 + W0dir^T . d  (folded into layer0 accumulator init)
        if (tid < HD) {
            float acc = ((const float*)(sm + B0S_OFF))[tid];
            const float* wd = (const float*)(sm + W0D_OFF);
            const float* sd = (const float*)(sm + SDIR_OFF);
            #pragma unroll
            for (int k = 0; k < DIRD; ++k) acc += sd[k] * wd[k * HD + tid];
            ((float*)(sm + BIASP_OFF))[tid] = acc;
        }
        __syncthreads();   // [B]

        // ================= per-warp GEMM chain (32 points/warp) =================
        float pc[2][2][3];
        #pragma unroll
        for (int a = 0; a < 2; ++a)
            #pragma unroll
            for (int q = 0; q < 2; ++q) { pc[a][q][0] = 0.f; pc[a][q][1] = 0.f; pc[a][q][2] = 0.f; }

        #pragma unroll
        for (int mt = 0; mt < 2; ++mt) {
            const int P0 = wid * 32 + mt * 16;

            // layer0 A fragments (hi & lo)
            uint32_t ah[2][4], al[2][4];
            #pragma unroll
            for (int ks = 0; ks < 2; ++ks)
                #pragma unroll
                for (int rr = 0; rr < 4; ++rr) {
                    const int row = P0 + g + ((rr & 1) << 3);
                    const int ku  = ks * 8 + tg + ((rr >> 1) << 2);
                    ah[ks][rr] = ((const uint32_t*)(sm + A0H_OFF))[row * A0_PITCH_U32 + ku];
                    al[ks][rr] = ((const uint32_t*)(sm + A0L_OFF))[row * A0_PITCH_U32 + ku];
                }

            float D[8][4];
            #pragma unroll
            for (int j = 0; j < 8; ++j) {
                const float2 bp = *(const float2*)((const float*)(sm + BIASP_OFF) + j * 8 + tg * 2);
                D[j][0] = bp.x; D[j][1] = bp.y; D[j][2] = bp.x; D[j][3] = bp.y;
            }
            // layer0: AhBh, AhBl, AlBh
            #pragma unroll
            for (int ks = 0; ks < 2; ++ks)
                #pragma unroll
                for (int j = 0; j < 8; ++j) mma_bf16(D[j], ah[ks], bf[(ks * 8 + j) * 32 + lane]);
            #pragma unroll
            for (int ks = 0; ks < 2; ++ks)
                #pragma unroll
                for (int j = 0; j < 8; ++j) mma_bf16(D[j], ah[ks], bf[(16 + ks * 8 + j) * 32 + lane]);
            #pragma unroll
            for (int ks = 0; ks < 2; ++ks)
                #pragma unroll
                for (int j = 0; j < 8; ++j) mma_bf16(D[j], al[ks], bf[(ks * 8 + j) * 32 + lane]);

            // relu -> layer1 A fragments (register-resident, D layout == A layout)
            uint32_t bh[4][4], bl[4][4];
            #pragma unroll
            for (int i = 0; i < 4; ++i)
                #pragma unroll
                for (int rr = 0; rr < 4; ++rr) {
                    const int jt = 2 * i + (rr >> 1);
                    const float f0 = fmaxf(D[jt][(rr & 1) * 2 + 0], 0.f);
                    const float f1 = fmaxf(D[jt][(rr & 1) * 2 + 1], 0.f);
                    split2(f0, f1, bh[i][rr], bl[i][rr]);
                }

            #pragma unroll
            for (int j = 0; j < 8; ++j) {
                const float2 bp = *(const float2*)((const float*)(sm + B1S_OFF) + j * 8 + tg * 2);
                D[j][0] = bp.x; D[j][1] = bp.y; D[j][2] = bp.x; D[j][3] = bp.y;
            }
            // layer1: AhBh, AhBl, AlBh
            #pragma unroll
            for (int ks = 0; ks < 4; ++ks)
                #pragma unroll
                for (int j = 0; j < 8; ++j) mma_bf16(D[j], bh[ks], bf[(32 + ks * 8 + j) * 32 + lane]);
            #pragma unroll
            for (int ks = 0; ks < 4; ++ks)
                #pragma unroll
                for (int j = 0; j < 8; ++j) mma_bf16(D[j], bh[ks], bf[(64 + ks * 8 + j) * 32 + lane]);
            #pragma unroll
            for (int ks = 0; ks < 4; ++ks)
                #pragma unroll
                for (int j = 0; j < 8; ++j) mma_bf16(D[j], bl[ks], bf[(32 + ks * 8 + j) * 32 + lane]);

            // layer2 partials (relu folded; b1 already in accumulator)
            #pragma unroll
            for (int j = 0; j < 8; ++j) {
                const float4 wa = ((const float4*)(sm + W2S_OFF))[j * 8 + tg * 2];
                const float4 wb = ((const float4*)(sm + W2S_OFF))[j * 8 + tg * 2 + 1];
                const float h00 = fmaxf(D[j][0], 0.f), h01 = fmaxf(D[j][1], 0.f);
                const float h10 = fmaxf(D[j][2], 0.f), h11 = fmaxf(D[j][3], 0.f);
                pc[mt][0][0] += h00 * wa.x + h01 * wb.x;
                pc[mt][0][1] += h00 * wa.y + h01 * wb.y;
                pc[mt][0][2] += h00 * wa.z + h01 * wb.z;
                pc[mt][1][0] += h10 * wa.x + h11 * wb.x;
                pc[mt][1][1] += h10 * wa.y + h11 * wb.y;
                pc[mt][1][2] += h10 * wa.z + h11 * wb.z;
            }
        }

        // reduce partials over the 4 threads sharing each point (tg bits)
        #pragma unroll
        for (int a = 0; a < 2; ++a)
            #pragma unroll
            for (int q = 0; q < 2; ++q)
                #pragma unroll
                for (int c = 0; c < 3; ++c) {
                    float v = pc[a][q][c];
                    v += __shfl_xor_sync(0xffffffffu, v, 1);
                    v += __shfl_xor_sync(0xffffffffu, v, 2);
                    pc[a][q][c] = v;
                }
        // each tg-thread takes one of the quad's 4 points
        float s0, s1, s2;
        if      (tg == 0) { s0 = pc[0][0][0]; s1 = pc[0][0][1]; s2 = pc[0][0][2]; }
        else if (tg == 1) { s0 = pc[0][1][0]; s1 = pc[0][1][1]; s2 = pc[0][1][2]; }
        else if (tg == 2) { s0 = pc[1][0][0]; s1 = pc[1][0][1]; s2 = pc[1][0][2]; }
        else              { s0 = pc[1][1][0]; s1 = pc[1][1][1]; s2 = pc[1][1][2]; }
        const int p = wid * 32 + ((tg >> 1) << 4) + ((tg & 1) << 3) + g;
        const float cwp = ((const float*)(sm + SCW_OFF))[p];
        // add b2 (the R3 bug), then sigmoid * compositing weight
        const float* bb2 = (const float*)(sm + SB2_OFF);
        s0 = cwp / (1.f + __expf(-(s0 + bb2[0])));
        s1 = cwp / (1.f + __expf(-(s1 + bb2[1])));
        s2 = cwp / (1.f + __expf(-(s2 + bb2[2])));
        #pragma unroll
        for (int o = 16; o; o >>= 1) {
            s0 += __shfl_xor_sync(0xffffffffu, s0, o);
            s1 += __shfl_xor_sync(0xffffffffu, s1, o);
            s2 += __shfl_xor_sync(0xffffffffu, s2, o);
        }
        if (lane == 0) {
            float* cr = (float*)(sm + CRED_OFF);
            cr[wid * 3 + 0] = s0; cr[wid * 3 + 1] = s1; cr[wid * 3 + 2] = s2;
        }
        __syncthreads();   // [C]
        if (tid < 3) {
            const float* cr = (const float*)(sm + CRED_OFF);
            outCol[(long long)b * 3 + tid] = cr[tid] + cr[3 + tid] + cr[6 + tid] + cr[9 + tid];
        }
    }
}

extern "C" void kernel_launch(void* const* d_in, const int* in_sizes, int n_in,
                              void* d_out, int out_size) {
    const int*   x  = (const int*)  d_in[0];
    const float* d  = (const float*)d_in[1];
    const float* gw = (const float*)d_in[2];
    const float* W0 = (const float*)d_in[3];
    const float* b0 = (const float*)d_in[4];
    const float* W1 = (const float*)d_in[5];
    const float* b1 = (const float*)d_in[6];
    const float* W2 = (const float*)d_in[7];
    const float* b2 = (const float*)d_in[8];

    const int B = in_sizes[1] / DIRD;
    float* out = (float*)d_out;
    float* outSig = out;
    float* outCol = out + (long long)B * TPB;

    cudaFuncSetAttribute(surf_mma, cudaFuncAttributeMaxDynamicSharedMemorySize, SMEM_TOTAL);
    const int blocks = (B + ROWS - 1) / ROWS;
    surf_mma<<<blocks, TPB, SMEM_TOTAL>>>(x, d, gw, W0, b0, W1, b1, W2, b2,
                                          outSig, outCol, B);
}

// round 5
// speedup vs baseline: 2.0280x; 1.3885x over previous
#include <cuda_runtime.h>
#include <cuda_bf16.h>
#include <cuda_fp16.h>
#include <cstdint>

#define TPB  128
#define ROWS 8
#define LVL  6
#define DIRD 16
#define HD   64
#define TABLE_N 4194304

// ---- repacked gather tables (built per launch; __device__ globals = legal scratch) ----
__device__ float g_c0[TABLE_N];        // channel 0, fp32 (sigma path, full precision)
__device__ uint2 g_c123[TABLE_N];      // channels 1..3 as fp16 (+pad), 8B/entry

// ---- dynamic smem offsets (bytes) ----
#define BF_OFF    0u        // B-fragment table: 96 slots * 32 lanes * 8B = 24576
#define A0H_OFF   24576u    // A0 hi tile: 128 rows * 80B = 10240
#define A0L_OFF   34816u    // A0 lo tile: 10240
#define W0D_OFF   45056u    // W0 dir part fp32 [16][64] = 4096
#define W2S_OFF   49152u    // W2 as float4[64] = 1024
#define BIASP_OFF 50176u    // bias' fp32[64]
#define B0S_OFF   50432u
#define B1S_OFF   50688u
#define SDIR_OFF  50944u    // fp32[16]
#define SS0_OFF   51008u    // fp32[128]
#define SCW_OFF   51520u    // fp32[128]
#define WRED_OFF  52032u    // fp32[4]
#define CRED_OFF  52048u    // fp32[12]
#define SB2_OFF   52096u    // fp32[4]
#define SMEM_TOTAL 52112u

#define A0_PITCH_U32 20     // 40 bf16 = 80B pitch (conflict-free fragment loads)

__global__ void repack_kernel(const float4* __restrict__ gw) {
    const int i = blockIdx.x * blockDim.x + threadIdx.x;
    if (i < TABLE_N) {
        const float4 v = gw[i];
        g_c0[i] = v.x;
        __half2 p01 = __floats2half2_rn(v.y, v.z);
        __half2 p23 = __floats2half2_rn(v.w, 0.f);
        uint2 u; u.x = *(uint32_t*)&p01; u.y = *(uint32_t*)&p23;
        g_c123[i] = u;
    }
}

// pack two floats to bf16x2 (hi) and residual bf16x2 (lo)
__device__ __forceinline__ void split2(float f0, float f1, uint32_t& hi, uint32_t& lo) {
    __nv_bfloat162 h = __floats2bfloat162_rn(f0, f1);
    hi = *(uint32_t*)&h;
    float2 hf = __bfloat1622float2(h);
    __nv_bfloat162 l = __floats2bfloat162_rn(f0 - hf.x, f1 - hf.y);
    lo = *(uint32_t*)&l;
}

__device__ __forceinline__ void mma_bf16(float d[4], const uint32_t a[4], uint2 b) {
    asm volatile("mma.sync.aligned.m16n8k16.row.col.f32.bf16.bf16.f32 "
        "{%0,%1,%2,%3}, {%4,%5,%6,%7}, {%8,%9}, {%0,%1,%2,%3};"
        : "+f"(d[0]), "+f"(d[1]), "+f"(d[2]), "+f"(d[3])
        : "r"(a[0]), "r"(a[1]), "r"(a[2]), "r"(a[3]), "r"(b.x), "r"(b.y));
}

__device__ __forceinline__ void load_idx(const int* __restrict__ xp, int* idx) {
    const int2 a = __ldg((const int2*)xp);
    const int2 b = __ldg((const int2*)(xp + 2));
    const int2 c = __ldg((const int2*)(xp + 4));
    idx[0] = a.x; idx[1] = a.y; idx[2] = b.x; idx[3] = b.y; idx[4] = c.x; idx[5] = c.y;
}

__device__ __forceinline__ void gather6(const int* idx, float* c0, uint2* c123) {
    #pragma unroll
    for (int l = 0; l < LVL; ++l) {
        c0[l]   = __ldg(g_c0 + idx[l]);
        c123[l] = __ldg(g_c123 + idx[l]);
    }
}

__global__ __launch_bounds__(TPB, 3) void surf_mma(
    const int*   __restrict__ x,
    const float* __restrict__ dirs,
    const float* __restrict__ W0, const float* __restrict__ b0,
    const float* __restrict__ W1, const float* __restrict__ b1,
    const float* __restrict__ W2, const float* __restrict__ b2,
    float* __restrict__ outSig, float* __restrict__ outCol, int Btot)
{
    extern __shared__ char sm[];
    const int tid = threadIdx.x, lane = tid & 31, wid = tid >> 5;
    const int g = lane >> 2, tg = lane & 3;

    // ================= one-time staging per CTA =================
    for (int i = tid; i < DIRD * HD; i += TPB)
        ((float*)(sm + W0D_OFF))[i] = W0[i];
    if (tid < HD) {
        float4 v; v.x = W2[tid * 3]; v.y = W2[tid * 3 + 1]; v.z = W2[tid * 3 + 2]; v.w = 0.f;
        ((float4*)(sm + W2S_OFF))[tid] = v;
        ((float*)(sm + B0S_OFF))[tid] = b0[tid];
        ((float*)(sm + B1S_OFF))[tid] = b1[tid];
    }
    if (tid < 3) ((float*)(sm + SB2_OFF))[tid] = b2[tid];
    // B fragments: layer0 slots 0..31 (hl*16+ks*8+j), layer1 slots 32..95
    uint2* bf = (uint2*)(sm + BF_OFF);
    for (int e = tid; e < 96 * 32; e += TPB) {
        const int s = e >> 5, ln = e & 31;
        const int lg = ln >> 2, ltg = ln & 3;
        int layer, hl, ks, j;
        if (s < 32) { layer = 0; hl = s >> 4; ks = (s >> 3) & 1; j = s & 7; }
        else { const int t2 = s - 32; layer = 1; hl = t2 >> 5; ks = (t2 >> 3) & 3; j = t2 & 7; }
        const int n = j * 8 + lg;
        uint32_t regs[2];
        #pragma unroll
        for (int rr = 0; rr < 2; ++rr) {
            const int k0 = ks * 16 + ltg * 2 + rr * 8;
            float wa, wb;
            if (layer == 0) {
                wa = (k0     < 18) ? W0[(16 + k0)     * HD + n] : 0.f;
                wb = (k0 + 1 < 18) ? W0[(16 + k0 + 1) * HD + n] : 0.f;
            } else {
                wa = W1[k0 * HD + n];
                wb = W1[(k0 + 1) * HD + n];
            }
            uint32_t hi, lo;
            split2(wa, wb, hi, lo);
            regs[rr] = hl ? lo : hi;
        }
        uint2 v; v.x = regs[0]; v.y = regs[1];
        bf[s * 32 + ln] = v;
    }
    // zero A0 pad columns 18..31 (u32 idx 9..15)
    for (int e = tid; e < TPB * 7; e += TPB) {
        const int p = e / 7, kk = 9 + (e % 7);
        ((uint32_t*)(sm + A0H_OFF))[p * A0_PITCH_U32 + kk] = 0u;
        ((uint32_t*)(sm + A0L_OFF))[p * A0_PITCH_U32 + kk] = 0u;
    }
    __syncthreads();

    // ================= pipelined row loop =================
    const int bBase = blockIdx.x * ROWS;
    int nidx[LVL];
    float nc0[LVL];
    uint2 nc123[LVL];
    {
        const int b0r = (bBase < Btot) ? bBase : (Btot - 1);
        load_idx(x + ((long long)b0r * TPB + tid) * LVL, nidx);
        gather6(nidx, nc0, nc123);
    }

    for (int r = 0; r < ROWS; ++r) {
        int b = bBase + r;
        if (b >= Btot) b = Btot - 1;   // duplicated identical work; uniform barriers

        if (tid < DIRD) ((float*)(sm + SDIR_OFF))[tid] = dirs[b * DIRD + tid];

        // prefetch next row's indices early (consumed after sync [B])
        const bool more = (r + 1 < ROWS);
        if (more) {
            int bn = bBase + r + 1;
            if (bn >= Btot) bn = Btot - 1;
            load_idx(x + ((long long)bn * TPB + tid) * LVL, nidx);
        }

        // ---- density from fp32 channel-0 (exact) ----
        float s = 1.f;
        #pragma unroll
        for (int l = 0; l < LVL; ++l) s *= fminf(fmaxf(nc0[l], 0.f), 1.f);
        s += 1e-4f;
        ((float*)(sm + SS0_OFF))[tid] = s;
        float m = s;
        #pragma unroll
        for (int o = 16; o; o >>= 1) m = fmaxf(m, __shfl_xor_sync(0xffffffffu, m, o));
        if (lane == 0) ((float*)(sm + WRED_OFF))[wid] = m;
        __syncthreads();   // [A]
        {
            const float* wr = (const float*)(sm + WRED_OFF);
            m = fmaxf(fmaxf(wr[0], wr[1]), fmaxf(wr[2], wr[3]));
        }
        const float inv_m = 1.f / m;
        const float sigma = s * inv_m;
        outSig[(long long)b * TPB + tid] = sigma;
        const float cw = (tid == 0) ? sigma
                         : (1.f - ((const float*)(sm + SS0_OFF))[tid - 1] * inv_m) * sigma;
        ((float*)(sm + SCW_OFF))[tid] = cw;

        // ---- write A0 (18 geo dims from fp16, hi/lo bf16, point-major) ----
        {
            float geo[18];
            #pragma unroll
            for (int l = 0; l < LVL; ++l) {
                const __half2 h01 = *(const __half2*)&nc123[l].x;
                const __half2 h23 = *(const __half2*)&nc123[l].y;
                const float2 f01 = __half22float2(h01);
                const float2 f23 = __half22float2(h23);
                geo[l * 3 + 0] = f01.x;
                geo[l * 3 + 1] = f01.y;
                geo[l * 3 + 2] = f23.x;
            }
            uint32_t* ah = (uint32_t*)(sm + A0H_OFF) + tid * A0_PITCH_U32;
            uint32_t* al = (uint32_t*)(sm + A0L_OFF) + tid * A0_PITCH_U32;
            #pragma unroll
            for (int kk = 0; kk < 9; ++kk) {
                uint32_t hi, lo;
                split2(geo[2 * kk], geo[2 * kk + 1], hi, lo);
                ah[kk] = hi; al[kk] = lo;
            }
        }
        // bias' = b0 + W0dir^T . d  (folded into layer0 accumulator init)
        if (tid < HD) {
            float acc = ((const float*)(sm + B0S_OFF))[tid];
            const float* wd = (const float*)(sm + W0D_OFF);
            const float* sd = (const float*)(sm + SDIR_OFF);
            #pragma unroll
            for (int k = 0; k < DIRD; ++k) acc += sd[k] * wd[k * HD + tid];
            ((float*)(sm + BIASP_OFF))[tid] = acc;
        }
        __syncthreads();   // [B]

        // issue next row's gathers now — latency hides under the MMA chain
        if (more) gather6(nidx, nc0, nc123);

        // ================= per-warp GEMM chain (32 points/warp) =================
        float pc[2][2][3];
        #pragma unroll
        for (int a = 0; a < 2; ++a)
            #pragma unroll
            for (int q = 0; q < 2; ++q) { pc[a][q][0] = 0.f; pc[a][q][1] = 0.f; pc[a][q][2] = 0.f; }

        #pragma unroll
        for (int mt = 0; mt < 2; ++mt) {
            const int P0 = wid * 32 + mt * 16;

            uint32_t ah[2][4], al[2][4];
            #pragma unroll
            for (int ks = 0; ks < 2; ++ks)
                #pragma unroll
                for (int rr = 0; rr < 4; ++rr) {
                    const int row = P0 + g + ((rr & 1) << 3);
                    const int ku  = ks * 8 + tg + ((rr >> 1) << 2);
                    ah[ks][rr] = ((const uint32_t*)(sm + A0H_OFF))[row * A0_PITCH_U32 + ku];
                    al[ks][rr] = ((const uint32_t*)(sm + A0L_OFF))[row * A0_PITCH_U32 + ku];
                }

            float D[8][4];
            #pragma unroll
            for (int j = 0; j < 8; ++j) {
                const float2 bp = *(const float2*)((const float*)(sm + BIASP_OFF) + j * 8 + tg * 2);
                D[j][0] = bp.x; D[j][1] = bp.y; D[j][2] = bp.x; D[j][3] = bp.y;
            }
            // layer0: AhBh, AhBl, AlBh
            #pragma unroll
            for (int ks = 0; ks < 2; ++ks)
                #pragma unroll
                for (int j = 0; j < 8; ++j) mma_bf16(D[j], ah[ks], bf[(ks * 8 + j) * 32 + lane]);
            #pragma unroll
            for (int ks = 0; ks < 2; ++ks)
                #pragma unroll
                for (int j = 0; j < 8; ++j) mma_bf16(D[j], ah[ks], bf[(16 + ks * 8 + j) * 32 + lane]);
            #pragma unroll
            for (int ks = 0; ks < 2; ++ks)
                #pragma unroll
                for (int j = 0; j < 8; ++j) mma_bf16(D[j], al[ks], bf[(ks * 8 + j) * 32 + lane]);

            // relu -> layer1 A fragments (register-resident, D layout == A layout)
            uint32_t bh[4][4], bl[4][4];
            #pragma unroll
            for (int i = 0; i < 4; ++i)
                #pragma unroll
                for (int rr = 0; rr < 4; ++rr) {
                    const int jt = 2 * i + (rr >> 1);
                    const float f0 = fmaxf(D[jt][(rr & 1) * 2 + 0], 0.f);
                    const float f1 = fmaxf(D[jt][(rr & 1) * 2 + 1], 0.f);
                    split2(f0, f1, bh[i][rr], bl[i][rr]);
                }

            #pragma unroll
            for (int j = 0; j < 8; ++j) {
                const float2 bp = *(const float2*)((const float*)(sm + B1S_OFF) + j * 8 + tg * 2);
                D[j][0] = bp.x; D[j][1] = bp.y; D[j][2] = bp.x; D[j][3] = bp.y;
            }
            // layer1: AhBh, AhBl, AlBh
            #pragma unroll
            for (int ks = 0; ks < 4; ++ks)
                #pragma unroll
                for (int j = 0; j < 8; ++j) mma_bf16(D[j], bh[ks], bf[(32 + ks * 8 + j) * 32 + lane]);
            #pragma unroll
            for (int ks = 0; ks < 4; ++ks)
                #pragma unroll
                for (int j = 0; j < 8; ++j) mma_bf16(D[j], bh[ks], bf[(64 + ks * 8 + j) * 32 + lane]);
            #pragma unroll
            for (int ks = 0; ks < 4; ++ks)
                #pragma unroll
                for (int j = 0; j < 8; ++j) mma_bf16(D[j], bl[ks], bf[(32 + ks * 8 + j) * 32 + lane]);

            // layer2 partials (relu folded; b1 already in accumulator)
            #pragma unroll
            for (int j = 0; j < 8; ++j) {
                const float4 wa = ((const float4*)(sm + W2S_OFF))[j * 8 + tg * 2];
                const float4 wb = ((const float4*)(sm + W2S_OFF))[j * 8 + tg * 2 + 1];
                const float h00 = fmaxf(D[j][0], 0.f), h01 = fmaxf(D[j][1], 0.f);
                const float h10 = fmaxf(D[j][2], 0.f), h11 = fmaxf(D[j][3], 0.f);
                pc[mt][0][0] += h00 * wa.x + h01 * wb.x;
                pc[mt][0][1] += h00 * wa.y + h01 * wb.y;
                pc[mt][0][2] += h00 * wa.z + h01 * wb.z;
                pc[mt][1][0] += h10 * wa.x + h11 * wb.x;
                pc[mt][1][1] += h10 * wa.y + h11 * wb.y;
                pc[mt][1][2] += h10 * wa.z + h11 * wb.z;
            }
        }

        // reduce partials over the 4 threads sharing each point
        #pragma unroll
        for (int a = 0; a < 2; ++a)
            #pragma unroll
            for (int q = 0; q < 2; ++q)
                #pragma unroll
                for (int c = 0; c < 3; ++c) {
                    float v = pc[a][q][c];
                    v += __shfl_xor_sync(0xffffffffu, v, 1);
                    v += __shfl_xor_sync(0xffffffffu, v, 2);
                    pc[a][q][c] = v;
                }
        float s0, s1, s2;
        if      (tg == 0) { s0 = pc[0][0][0]; s1 = pc[0][0][1]; s2 = pc[0][0][2]; }
        else if (tg == 1) { s0 = pc[0][1][0]; s1 = pc[0][1][1]; s2 = pc[0][1][2]; }
        else if (tg == 2) { s0 = pc[1][0][0]; s1 = pc[1][0][1]; s2 = pc[1][0][2]; }
        else              { s0 = pc[1][1][0]; s1 = pc[1][1][1]; s2 = pc[1][1][2]; }
        const int p = wid * 32 + ((tg >> 1) << 4) + ((tg & 1) << 3) + g;
        const float cwp = ((const float*)(sm + SCW_OFF))[p];
        const float* bb2 = (const float*)(sm + SB2_OFF);
        s0 = cwp / (1.f + __expf(-(s0 + bb2[0])));
        s1 = cwp / (1.f + __expf(-(s1 + bb2[1])));
        s2 = cwp / (1.f + __expf(-(s2 + bb2[2])));
        #pragma unroll
        for (int o = 16; o; o >>= 1) {
            s0 += __shfl_xor_sync(0xffffffffu, s0, o);
            s1 += __shfl_xor_sync(0xffffffffu, s1, o);
            s2 += __shfl_xor_sync(0xffffffffu, s2, o);
        }
        if (lane == 0) {
            float* cr = (float*)(sm + CRED_OFF);
            cr[wid * 3 + 0] = s0; cr[wid * 3 + 1] = s1; cr[wid * 3 + 2] = s2;
        }
        __syncthreads();   // [C]
        if (tid < 3) {
            const float* cr = (const float*)(sm + CRED_OFF);
            outCol[(long long)b * 3 + tid] = cr[tid] + cr[3 + tid] + cr[6 + tid] + cr[9 + tid];
        }
    }
}

extern "C" void kernel_launch(void* const* d_in, const int* in_sizes, int n_in,
                              void* d_out, int out_size) {
    const int*   x  = (const int*)  d_in[0];
    const float* d  = (const float*)d_in[1];
    const float* gw = (const float*)d_in[2];
    const float* W0 = (const float*)d_in[3];
    const float* b0 = (const float*)d_in[4];
    const float* W1 = (const float*)d_in[5];
    const float* b1 = (const float*)d_in[6];
    const float* W2 = (const float*)d_in[7];
    const float* b2 = (const float*)d_in[8];

    const int B = in_sizes[1] / DIRD;
    float* out = (float*)d_out;
    float* outSig = out;
    float* outCol = out + (long long)B * TPB;

    // per-launch table repack (graph-capturable, deterministic)
    repack_kernel<<<(TABLE_N + 255) / 256, 256>>>((const float4*)gw);

    cudaFuncSetAttribute(surf_mma, cudaFuncAttributeMaxDynamicSharedMemorySize, SMEM_TOTAL);
    const int blocks = (B + ROWS - 1) / ROWS;
    surf_mma<<<blocks, TPB, SMEM_TOTAL>>>(x, d, W0, b0, W1, b1, W2, b2,
                                          outSig, outCol, B);
}